// round 16
// baseline (speedup 1.0000x reference)
#include <cuda_runtime.h>
#include <cuda_fp16.h>
#include <cstdint>

#define Hd 128
#define Nn 512
#define Bb 2
#define TJ 128
#define NTE 512     // edge kernel threads (16 warps)
#define NT 256      // other kernels
#define LDK 136     // padded row stride in halfs
#define NTILES (Nn / TJ)

// ---------------- device scratch (no allocations allowed) ------------------
__device__ float  g_A[Bb * Nn * Hd];      // h @ eW1[0:128] + eb1  (f32)
__device__ __half g_Bvh[Bb * Nn * Hd];    // h @ eW1[128:256]      (f16)
__device__ float  g_magg[Bb * Nn * Hd];   // sum_j m_ij
__device__ uint4  g_W2h[2176];            // eW2^T f16 [n][k] pad LDK
__device__ uint4  g_C1h[2176];            // cW1^T f16 [n][k] pad LDK

__device__ __forceinline__ float tanh_f(float x) {
    float r;
    asm("tanh.approx.f32 %0, %1;" : "=f"(r) : "f"(x));
    return r;
}
__device__ __forceinline__ float silu_f(float v) {
    float h = 0.5f * v;
    return fmaf(h, tanh_f(h), h);
}
__device__ __forceinline__ __half2 silu_h2(__half2 v) {
    __half2 hh = __hmul2(v, __half2half2(__float2half_rn(0.5f)));
    __half2 t;
    asm("tanh.approx.f16x2 %0, %1;"
        : "=r"(*reinterpret_cast<uint32_t*>(&t))
        : "r"(*reinterpret_cast<const uint32_t*>(&hh)));
    return __hfma2(hh, t, hh);
}
__device__ __forceinline__ uint32_t h2u(__half2 h) {
    return *reinterpret_cast<uint32_t*>(&h);
}
__device__ __forceinline__ void mma16816(float* c,
                                         uint32_t a0, uint32_t a1, uint32_t a2, uint32_t a3,
                                         uint32_t b0, uint32_t b1) {
    asm volatile(
        "mma.sync.aligned.m16n8k16.row.col.f32.f16.f16.f32 "
        "{%0,%1,%2,%3},{%4,%5,%6,%7},{%8,%9},{%0,%1,%2,%3};"
        : "+f"(c[0]), "+f"(c[1]), "+f"(c[2]), "+f"(c[3])
        : "r"(a0), "r"(a1), "r"(a2), "r"(a3), "r"(b0), "r"(b1));
}

// ---------------------------------------------------------------------------
// Weight conversion (once, tiny)
// ---------------------------------------------------------------------------
__global__ void convert_w_kernel(const float* __restrict__ eW2,
                                 const float* __restrict__ cW1) {
    int idx = blockIdx.x * blockDim.x + threadIdx.x;  // k*128+n
    if (idx >= Hd * Hd) return;
    int k = idx >> 7, n = idx & 127;
    ((__half*)g_W2h)[n * LDK + k] = __float2half(eW2[idx]);
    ((__half*)g_C1h)[n * LDK + k] = __float2half(cW1[idx]);
}

// ---------------------------------------------------------------------------
// Precompute A (f32) / Bv (f16): 16 rows per CTA, 256 threads
// ---------------------------------------------------------------------------
__global__ void precompute_kernel(const float* __restrict__ h,
                                  const float* __restrict__ eW1,
                                  const float* __restrict__ eb1) {
    __shared__ float sh[16][Hd];
    const int row0 = blockIdx.x * 16;
    const int t = threadIdx.x, k = t & 127, sel = t >> 7;
    for (int idx = t; idx < 16 * Hd; idx += NT)
        sh[idx >> 7][idx & 127] = h[row0 * Hd + idx];
    __syncthreads();
    float acc[16];
#pragma unroll
    for (int i = 0; i < 16; i++) acc[i] = sel ? 0.f : eb1[k];
    const float* w = eW1 + sel * Hd * Hd + k;
#pragma unroll 4
    for (int r = 0; r < Hd; r++) {
        float wv = w[r * Hd];
#pragma unroll
        for (int i = 0; i < 16; i++) acc[i] += sh[i][r] * wv;
    }
    if (sel) {
#pragma unroll
        for (int i = 0; i < 16; i++) g_Bvh[(row0 + i) * Hd + k] = __float2half(acc[i]);
    } else {
#pragma unroll
        for (int i = 0; i < 16; i++) g_A[(row0 + i) * Hd + k] = acc[i];
    }
}

// ---------------------------------------------------------------------------
// Edge kernel: 512 threads (16 warps), warp tile 16x64, occ 2
// ---------------------------------------------------------------------------
struct __align__(16) ESmem {
    __half W2[Hd * LDK];
    __half C1[Hd * LDK];
    __half T1[TJ * LDK];   // activation tile (in-place reuse)
    float sAi[Hd], sWd[Hd], sEb2[Hd], sCb1[Hd], sCw2[Hd];
    float SD[TJ];
    float sx3[TJ * 3];
    float P[2][TJ];
    float mred[8][Hd];     // magg accumulators per rowgroup
    float csum[4][3];
};

// acc[0..7][4]: rows rowbase+g, rowbase+g+8 (16 rows), cols colbase..+64
__device__ __forceinline__ void gemm_acc(const __half* __restrict__ A,
                                         const __half* __restrict__ W,
                                         float acc[8][4],
                                         int g, int tig, int rowbase, int colbase) {
    const uint32_t* Au = reinterpret_cast<const uint32_t*>(A);
    const uint32_t* Wu = reinterpret_cast<const uint32_t*>(W);
    const int ra = (rowbase + g) * (LDK / 2);
    const int rb = (rowbase + g + 8) * (LDK / 2);
#pragma unroll
    for (int ks = 0; ks < 8; ks++) {
        const int kh = ks * 8;
        uint32_t a0 = Au[ra + kh + tig];
        uint32_t a1 = Au[rb + kh + tig];
        uint32_t a2 = Au[ra + kh + 4 + tig];
        uint32_t a3 = Au[rb + kh + 4 + tig];
#pragma unroll
        for (int nb = 0; nb < 8; nb++) {
            const int n = colbase + nb * 8 + g;
            const int wb = n * (LDK / 2) + kh;
            uint32_t b0 = Wu[wb + tig];
            uint32_t b1 = Wu[wb + 4 + tig];
            mma16816(acc[nb], a0, a1, a2, a3, b0, b1);
        }
    }
}

__global__ void __launch_bounds__(NTE, 2)
edge_kernel(const float* __restrict__ x,
            const float* __restrict__ eW1,
            const float* __restrict__ eb2, const float* __restrict__ cb1,
            const float* __restrict__ cW2,
            float* __restrict__ xout) {
    extern __shared__ __align__(16) unsigned char sm_raw[];
    ESmem* S = reinterpret_cast<ESmem*>(sm_raw);

    const int i = blockIdx.x, b = blockIdx.y;
    const int t = threadIdx.x;
    const int lane = t & 31, wid = t >> 5;
    const int g = lane >> 2, tig = lane & 3;
    const int rg = wid & 7;               // 8 rowgroups of 16 rows
    const int rowbase = rg * 16;
    const int cg = wid >> 3;              // 2 colgroups of 64 cols
    const int colbase = cg * 64;
    const int row_i = b * Nn + i;

    {
        uint4* dw = (uint4*)S->W2;
        uint4* dc = (uint4*)S->C1;
        for (int idx = t; idx < 2176; idx += NTE) {
            dw[idx] = g_W2h[idx];
            dc[idx] = g_C1h[idx];
        }
    }
    for (int idx = t; idx < Hd; idx += NTE) {
        S->sAi[idx]  = g_A[row_i * Hd + idx];
        S->sWd[idx]  = eW1[256 * Hd + idx];
        S->sEb2[idx] = eb2[idx];
        S->sCb1[idx] = cb1[idx];
        S->sCw2[idx] = cW2[idx];
    }
    for (int idx = t; idx < 8 * Hd; idx += NTE)
        S->mred[idx >> 7][idx & 127] = 0.f;

    const float xi0 = x[row_i * 3 + 0];
    const float xi1 = x[row_i * 3 + 1];
    const float xi2 = x[row_i * 3 + 2];
    float cx = 0.f, cy = 0.f, cz = 0.f;
    __syncthreads();

    for (int jt = 0; jt < NTILES; jt++) {
        const int j0 = jt * TJ;

        // Phase A: distances + x_j
        if (t < TJ) {
            const int j = j0 + t;
            float x0 = x[(b * Nn + j) * 3 + 0];
            float x1 = x[(b * Nn + j) * 3 + 1];
            float x2 = x[(b * Nn + j) * 3 + 2];
            S->sx3[t * 3 + 0] = x0; S->sx3[t * 3 + 1] = x1; S->sx3[t * 3 + 2] = x2;
            float dx = xi0 - x0, dy = xi1 - x1, dz = xi2 - x2;
            S->SD[t] = dx * dx + dy * dy + dz * dz;
        }
        __syncthreads();

        // Phase B: T1 = silu_h2(f16(Ai + Bv_j + d*Wd)), 128x128
#pragma unroll
        for (int it = 0; it < 4; it++) {
            const int idx = t * 8 + it * NTE * 8;
            const int m = idx >> 7, k = idx & 127;
            uint4 braw = *(const uint4*)&g_Bvh[(size_t)(b * Nn + j0 + m) * Hd + k];
            const __half2* bh = reinterpret_cast<const __half2*>(&braw);
            const float d = S->SD[m];
            uint4 pk;
            uint32_t* pko = reinterpret_cast<uint32_t*>(&pk);
#pragma unroll
            for (int q = 0; q < 4; q++) {
                float2 bv = __half22float2(bh[q]);
                const int kk = k + 2 * q;
                float p0 = S->sAi[kk]     + bv.x + d * S->sWd[kk];
                float p1 = S->sAi[kk + 1] + bv.y + d * S->sWd[kk + 1];
                pko[q] = h2u(silu_h2(__floats2half2_rn(p0, p1)));
            }
            *(uint4*)&S->T1[m * LDK + k] = pk;
        }
        __syncthreads();

        // GEMM1: acc = T1 @ eW2
        {
            float acc[8][4];
#pragma unroll
            for (int q = 0; q < 8; q++)
#pragma unroll
                for (int c = 0; c < 4; c++) acc[q][c] = 0.f;
            gemm_acc(S->T1, S->W2, acc, g, tig, rowbase, colbase);
            __syncthreads();   // all warps done reading T1 before aliased write

            // Epilogue 1 (in place): T1 = silu_h2(acc + eb2); magg via shfl->SMEM
            const int r0 = rowbase + g, r1 = r0 + 8;
#pragma unroll
            for (int nb = 0; nb < 8; nb++) {
                const int col = colbase + nb * 8 + 2 * tig;
                const float bb0 = S->sEb2[col], bb1 = S->sEb2[col + 1];
                __half2 s0 = silu_h2(__floats2half2_rn(acc[nb][0] + bb0, acc[nb][1] + bb1));
                __half2 s1 = silu_h2(__floats2half2_rn(acc[nb][2] + bb0, acc[nb][3] + bb1));
                *(uint32_t*)&S->T1[r0 * LDK + col] = h2u(s0);
                *(uint32_t*)&S->T1[r1 * LDK + col] = h2u(s1);
                float2 f0 = __half22float2(s0);
                float2 f1 = __half22float2(s1);
                float m0 = f0.x + f1.x;
                float m1 = f0.y + f1.y;
                m0 += __shfl_down_sync(0xffffffffu, m0, 4);
                m0 += __shfl_down_sync(0xffffffffu, m0, 8);
                m0 += __shfl_down_sync(0xffffffffu, m0, 16);
                m1 += __shfl_down_sync(0xffffffffu, m1, 4);
                m1 += __shfl_down_sync(0xffffffffu, m1, 8);
                m1 += __shfl_down_sync(0xffffffffu, m1, 16);
                if (lane < 4) {
                    const int c2 = colbase + nb * 8 + 2 * lane;
                    S->mred[rg][c2]     += m0;
                    S->mred[rg][c2 + 1] += m1;
                }
            }
        }
        __syncthreads();

        // GEMM2 + fused dot: P[cg][row] = dot(silu_h2(T1 @ cW1 + cb1), cW2)
        {
            float acc[8][4];
#pragma unroll
            for (int q = 0; q < 8; q++)
#pragma unroll
                for (int c = 0; c < 4; c++) acc[q][c] = 0.f;
            gemm_acc(S->T1, S->C1, acc, g, tig, rowbase, colbase);
            float d0 = 0.f, d1 = 0.f;
#pragma unroll
            for (int nb = 0; nb < 8; nb++) {
                const int col = colbase + nb * 8 + 2 * tig;
                const float w0 = S->sCw2[col], w1 = S->sCw2[col + 1];
                const float bb0 = S->sCb1[col], bb1 = S->sCb1[col + 1];
                float2 f0 = __half22float2(silu_h2(__floats2half2_rn(acc[nb][0] + bb0, acc[nb][1] + bb1)));
                float2 f1 = __half22float2(silu_h2(__floats2half2_rn(acc[nb][2] + bb0, acc[nb][3] + bb1)));
                d0 += f0.x * w0 + f0.y * w1;
                d1 += f1.x * w0 + f1.y * w1;
            }
            d0 += __shfl_xor_sync(0xffffffffu, d0, 1); d0 += __shfl_xor_sync(0xffffffffu, d0, 2);
            d1 += __shfl_xor_sync(0xffffffffu, d1, 1); d1 += __shfl_xor_sync(0xffffffffu, d1, 2);
            if (tig == 0) {
                S->P[cg][rowbase + g]     = d0;
                S->P[cg][rowbase + g + 8] = d1;
            }
        }
        __syncthreads();

        // coord accumulation over this tile
        if (t < TJ) {
            float wv = tanh_f(S->P[0][t] + S->P[1][t]);
            cx += (xi0 - S->sx3[t * 3 + 0]) * wv;
            cy += (xi1 - S->sx3[t * 3 + 1]) * wv;
            cz += (xi2 - S->sx3[t * 3 + 2]) * wv;
        }
        __syncthreads();
    }

    // coord cross-warp reduce (warps 0-3 hold partials)
    if (t < TJ) {
#pragma unroll
        for (int off = 16; off; off >>= 1) {
            cx += __shfl_down_sync(0xffffffffu, cx, off);
            cy += __shfl_down_sync(0xffffffffu, cy, off);
            cz += __shfl_down_sync(0xffffffffu, cz, off);
        }
        if (lane == 0) { S->csum[wid][0] = cx; S->csum[wid][1] = cy; S->csum[wid][2] = cz; }
    }
    __syncthreads();

    if (t < Hd) {
        float s = 0.f;
#pragma unroll
        for (int r = 0; r < 8; r++) s += S->mred[r][t];
        g_magg[row_i * Hd + t] = s;
    }
    if (t == 0) {
        const float inv = 1.0f / (float)(Nn - 1);
        float s0 = S->csum[0][0] + S->csum[1][0] + S->csum[2][0] + S->csum[3][0];
        float s1 = S->csum[0][1] + S->csum[1][1] + S->csum[2][1] + S->csum[3][1];
        float s2 = S->csum[0][2] + S->csum[1][2] + S->csum[2][2] + S->csum[3][2];
        xout[row_i * 3 + 0] = xi0 + s0 * inv;
        xout[row_i * 3 + 1] = xi1 + s1 * inv;
        xout[row_i * 3 + 2] = xi2 + s2 * inv;
    }
}

// ---------------------------------------------------------------------------
// Node MLP: weights in SMEM, grid=128 (8 rows/CTA), float4 chunked loads
// ---------------------------------------------------------------------------
#define NODE_NR 8
struct __align__(16) NSmem {
    float W1[2 * Hd * Hd];
    float W2[Hd * Hd];
    float IN[NODE_NR][2 * Hd];
    float T[NODE_NR][Hd];
};

__global__ void __launch_bounds__(NT, 1)
node_kernel(const float* __restrict__ h,
            const float* __restrict__ nW1, const float* __restrict__ nb1,
            const float* __restrict__ nW2, const float* __restrict__ nb2,
            float* __restrict__ hout) {
    extern __shared__ __align__(16) unsigned char nsm_raw[];
    NSmem* S = reinterpret_cast<NSmem*>(nsm_raw);
    const int row0 = blockIdx.x * NODE_NR;
    const int t = threadIdx.x;

    {
        const uint4* s1 = (const uint4*)nW1;
        const uint4* s2 = (const uint4*)nW2;
        uint4* d1 = (uint4*)S->W1;
        uint4* d2 = (uint4*)S->W2;
        for (int idx = t; idx < 2 * Hd * Hd / 4; idx += NT) d1[idx] = s1[idx];
        for (int idx = t; idx < Hd * Hd / 4; idx += NT) d2[idx] = s2[idx];
    }
    for (int idx = t; idx < NODE_NR * 2 * Hd; idx += NT) {
        const int r = idx >> 8, c = idx & 255;
        S->IN[r][c] = (c < Hd) ? h[(row0 + r) * Hd + c]
                               : g_magg[(row0 + r) * Hd + (c - Hd)];
    }
    __syncthreads();

    const int k = t & 127, half = t >> 7;
    const int rb = half * 4;
    float acc[4];
    {
        const float b = nb1[k];
#pragma unroll
        for (int r = 0; r < 4; r++) acc[r] = b;
    }
#pragma unroll 4
    for (int c0 = 0; c0 < 2 * Hd; c0 += 4) {
        float4 in0 = *(const float4*)&S->IN[rb + 0][c0];
        float4 in1 = *(const float4*)&S->IN[rb + 1][c0];
        float4 in2 = *(const float4*)&S->IN[rb + 2][c0];
        float4 in3 = *(const float4*)&S->IN[rb + 3][c0];
        float w0 = S->W1[(c0 + 0) * Hd + k];
        float w1 = S->W1[(c0 + 1) * Hd + k];
        float w2 = S->W1[(c0 + 2) * Hd + k];
        float w3 = S->W1[(c0 + 3) * Hd + k];
        acc[0] = fmaf(in0.x, w0, fmaf(in0.y, w1, fmaf(in0.z, w2, fmaf(in0.w, w3, acc[0]))));
        acc[1] = fmaf(in1.x, w0, fmaf(in1.y, w1, fmaf(in1.z, w2, fmaf(in1.w, w3, acc[1]))));
        acc[2] = fmaf(in2.x, w0, fmaf(in2.y, w1, fmaf(in2.z, w2, fmaf(in2.w, w3, acc[2]))));
        acc[3] = fmaf(in3.x, w0, fmaf(in3.y, w1, fmaf(in3.z, w2, fmaf(in3.w, w3, acc[3]))));
    }
#pragma unroll
    for (int r = 0; r < 4; r++) S->T[rb + r][k] = silu_f(acc[r]);
    __syncthreads();
    float o[4];
    {
        const float b = nb2[k];
#pragma unroll
        for (int r = 0; r < 4; r++) o[r] = b;
    }
#pragma unroll 4
    for (int c0 = 0; c0 < Hd; c0 += 4) {
        float4 t0 = *(const float4*)&S->T[rb + 0][c0];
        float4 t1 = *(const float4*)&S->T[rb + 1][c0];
        float4 t2 = *(const float4*)&S->T[rb + 2][c0];
        float4 t3 = *(const float4*)&S->T[rb + 3][c0];
        float w0 = S->W2[(c0 + 0) * Hd + k];
        float w1 = S->W2[(c0 + 1) * Hd + k];
        float w2 = S->W2[(c0 + 2) * Hd + k];
        float w3 = S->W2[(c0 + 3) * Hd + k];
        o[0] = fmaf(t0.x, w0, fmaf(t0.y, w1, fmaf(t0.z, w2, fmaf(t0.w, w3, o[0]))));
        o[1] = fmaf(t1.x, w0, fmaf(t1.y, w1, fmaf(t1.z, w2, fmaf(t1.w, w3, o[1]))));
        o[2] = fmaf(t2.x, w0, fmaf(t2.y, w1, fmaf(t2.z, w2, fmaf(t2.w, w3, o[2]))));
        o[3] = fmaf(t3.x, w0, fmaf(t3.y, w1, fmaf(t3.z, w2, fmaf(t3.w, w3, o[3]))));
    }
#pragma unroll
    for (int r = 0; r < 4; r++)
        hout[(row0 + rb + r) * Hd + k] = S->IN[rb + r][k] + o[r];
}

// ---------------------------------------------------------------------------
extern "C" void kernel_launch(void* const* d_in, const int* in_sizes, int n_in,
                              void* d_out, int out_size) {
    const float* h   = (const float*)d_in[0];
    const float* x   = (const float*)d_in[1];
    const float* eW1 = (const float*)d_in[2];
    const float* eb1 = (const float*)d_in[3];
    const float* eW2 = (const float*)d_in[4];
    const float* eb2 = (const float*)d_in[5];
    const float* nW1 = (const float*)d_in[6];
    const float* nb1 = (const float*)d_in[7];
    const float* nW2 = (const float*)d_in[8];
    const float* nb2 = (const float*)d_in[9];
    const float* cW1 = (const float*)d_in[10];
    const float* cb1 = (const float*)d_in[11];
    const float* cW2 = (const float*)d_in[12];

    float* out  = (float*)d_out;
    float* hout = out;
    float* xout = out + Bb * Nn * Hd;

    convert_w_kernel<<<64, 256>>>(eW2, cW1);
    precompute_kernel<<<Bb * Nn / 16, NT>>>(h, eW1, eb1);

    const int smem = (int)sizeof(ESmem);
    cudaFuncSetAttribute(edge_kernel, cudaFuncAttributeMaxDynamicSharedMemorySize, smem);
    dim3 grid(Nn, Bb);
    edge_kernel<<<grid, NTE, smem>>>(x, eW1, eb2, cb1, cW2, xout);

    const int nsmem = (int)sizeof(NSmem);
    cudaFuncSetAttribute(node_kernel, cudaFuncAttributeMaxDynamicSharedMemorySize, nsmem);
    node_kernel<<<Bb * Nn / NODE_NR, NT, nsmem>>>(h, nW1, nb1, nW2, nb2, hout);
}

// round 17
// speedup vs baseline: 1.1867x; 1.1867x over previous
#include <cuda_runtime.h>
#include <cuda_fp16.h>
#include <cstdint>

#define Hd 128
#define Nn 512
#define Bb 2
#define TJ 128
#define NT 256
#define LDK 136     // padded row stride in halfs: 272B/row = 4-bank shift, conflict-free
#define LDKB 272    // row stride bytes
#define NTILES (Nn / TJ)

// ---------------- device scratch (no allocations allowed) ------------------
__device__ float  g_A[Bb * Nn * Hd];      // h @ eW1[0:128] + eb1  (f32)
__device__ __half g_Bvh[Bb * Nn * Hd];    // h @ eW1[128:256]      (f16)
__device__ float  g_magg[Bb * Nn * Hd];   // sum_j m_ij
__device__ uint4  g_W2h[2176];            // eW2^T f16 [n][k] pad LDK
__device__ uint4  g_C1h[2176];            // cW1^T f16 [n][k] pad LDK

__device__ __forceinline__ float tanh_f(float x) {
    float r;
    asm("tanh.approx.f32 %0, %1;" : "=f"(r) : "f"(x));
    return r;
}
__device__ __forceinline__ float silu_f(float v) {
    float h = 0.5f * v;
    return fmaf(h, tanh_f(h), h);
}
__device__ __forceinline__ __half2 silu_h2(__half2 v) {
    __half2 hh = __hmul2(v, __half2half2(__float2half_rn(0.5f)));
    __half2 t;
    asm("tanh.approx.f16x2 %0, %1;"
        : "=r"(*reinterpret_cast<uint32_t*>(&t))
        : "r"(*reinterpret_cast<const uint32_t*>(&hh)));
    return __hfma2(hh, t, hh);
}
__device__ __forceinline__ uint32_t h2u(__half2 h) {
    return *reinterpret_cast<uint32_t*>(&h);
}
__device__ __forceinline__ uint32_t smem_u32(const void* p) {
    uint32_t a;
    asm("{ .reg .u64 t; cvta.to.shared.u64 t, %1; cvt.u32.u64 %0, t; }" : "=r"(a) : "l"(p));
    return a;
}
__device__ __forceinline__ void mma16816(float* c,
                                         uint32_t a0, uint32_t a1, uint32_t a2, uint32_t a3,
                                         uint32_t b0, uint32_t b1) {
    asm volatile(
        "mma.sync.aligned.m16n8k16.row.col.f32.f16.f16.f32 "
        "{%0,%1,%2,%3},{%4,%5,%6,%7},{%8,%9},{%0,%1,%2,%3};"
        : "+f"(c[0]), "+f"(c[1]), "+f"(c[2]), "+f"(c[3])
        : "r"(a0), "r"(a1), "r"(a2), "r"(a3), "r"(b0), "r"(b1));
}
__device__ __forceinline__ void ldsm4(uint32_t& r0, uint32_t& r1, uint32_t& r2, uint32_t& r3,
                                      uint32_t addr) {
    asm volatile("ldmatrix.sync.aligned.m8n8.x4.shared.b16 {%0,%1,%2,%3}, [%4];"
                 : "=r"(r0), "=r"(r1), "=r"(r2), "=r"(r3) : "r"(addr));
}

// ---------------------------------------------------------------------------
// Weight conversion (once, tiny)
// ---------------------------------------------------------------------------
__global__ void convert_w_kernel(const float* __restrict__ eW2,
                                 const float* __restrict__ cW1) {
    int idx = blockIdx.x * blockDim.x + threadIdx.x;  // k*128+n
    if (idx >= Hd * Hd) return;
    int k = idx >> 7, n = idx & 127;
    ((__half*)g_W2h)[n * LDK + k] = __float2half(eW2[idx]);
    ((__half*)g_C1h)[n * LDK + k] = __float2half(cW1[idx]);
}

// ---------------------------------------------------------------------------
// Precompute A (f32) / Bv (f16): 16 rows per CTA, 256 threads
// ---------------------------------------------------------------------------
__global__ void precompute_kernel(const float* __restrict__ h,
                                  const float* __restrict__ eW1,
                                  const float* __restrict__ eb1) {
    __shared__ float sh[16][Hd];
    const int row0 = blockIdx.x * 16;
    const int t = threadIdx.x, k = t & 127, sel = t >> 7;
    for (int idx = t; idx < 16 * Hd; idx += NT)
        sh[idx >> 7][idx & 127] = h[row0 * Hd + idx];
    __syncthreads();
    float acc[16];
#pragma unroll
    for (int i = 0; i < 16; i++) acc[i] = sel ? 0.f : eb1[k];
    const float* w = eW1 + sel * Hd * Hd + k;
#pragma unroll 4
    for (int r = 0; r < Hd; r++) {
        float wv = w[r * Hd];
#pragma unroll
        for (int i = 0; i < 16; i++) acc[i] += sh[i][r] * wv;
    }
    if (sel) {
#pragma unroll
        for (int i = 0; i < 16; i++) g_Bvh[(row0 + i) * Hd + k] = __float2half(acc[i]);
    } else {
#pragma unroll
        for (int i = 0; i < 16; i++) g_A[(row0 + i) * Hd + k] = acc[i];
    }
}

// ---------------------------------------------------------------------------
// Edge kernel: R13 shape (NT=256, warp tile 32x64, occ 2) + ldmatrix loads
// ---------------------------------------------------------------------------
struct __align__(16) ESmem {
    __half W2[Hd * LDK];
    __half C1[Hd * LDK];
    __half T1[TJ * LDK];   // activation tile (in-place reuse)
    float sAi[Hd], sWd[Hd], sEb2[Hd], sCb1[Hd], sCw2[Hd];
    float SD[TJ];
    float sx3[TJ * 3];
    float P[2][TJ];
    float mred[4][Hd];
    float csum[4][3];
};

// acc[0..7]: rows rowbase..+15 ; acc[8..15]: rows rowbase+16..+31
// aAddr: per-lane LDSM address into A tile (row block at rowbase)
// bAddr: per-lane LDSM address into W tile (col block at colbase)
__device__ __forceinline__ void gemm_acc(uint32_t aAddr, uint32_t bAddr,
                                         float acc[16][4]) {
#pragma unroll
    for (int ks = 0; ks < 8; ks++) {
        const uint32_t ko = ks * 32;   // 16 halves per k-step
        uint32_t a0, a1, a2, a3, a4, a5, a6, a7;
        ldsm4(a0, a1, a2, a3, aAddr + ko);
        ldsm4(a4, a5, a6, a7, aAddr + 16 * LDKB + ko);
#pragma unroll
        for (int np = 0; np < 4; np++) {
            uint32_t b0, b1, b2, b3;
            ldsm4(b0, b1, b2, b3, bAddr + np * 16 * LDKB + ko);
            mma16816(acc[2 * np],         a0, a1, a2, a3, b0, b1);
            mma16816(acc[2 * np + 1],     a0, a1, a2, a3, b2, b3);
            mma16816(acc[8 + 2 * np],     a4, a5, a6, a7, b0, b1);
            mma16816(acc[8 + 2 * np + 1], a4, a5, a6, a7, b2, b3);
        }
    }
}

__global__ void __launch_bounds__(NT, 2)
edge_kernel(const float* __restrict__ x,
            const float* __restrict__ eW1,
            const float* __restrict__ eb2, const float* __restrict__ cb1,
            const float* __restrict__ cW2,
            float* __restrict__ xout) {
    extern __shared__ __align__(16) unsigned char sm_raw[];
    ESmem* S = reinterpret_cast<ESmem*>(sm_raw);

    const int i = blockIdx.x, b = blockIdx.y;
    const int t = threadIdx.x;
    const int lane = t & 31, wid = t >> 5;
    const int g = lane >> 2, tig = lane & 3;
    const int rowbase = (wid & 3) * 32;   // 4 rowgroups of 32 rows
    const int colbase = (wid >> 2) * 64;  // 2 colgroups of 64 cols
    const int cg = wid >> 2;
    const int row_i = b * Nn + i;

    {
        uint4* dw = (uint4*)S->W2;
        uint4* dc = (uint4*)S->C1;
        for (int idx = t; idx < 2176; idx += NT) {
            dw[idx] = g_W2h[idx];
            dc[idx] = g_C1h[idx];
        }
    }
    for (int idx = t; idx < Hd; idx += NT) {
        S->sAi[idx]  = g_A[row_i * Hd + idx];
        S->sWd[idx]  = eW1[256 * Hd + idx];
        S->sEb2[idx] = eb2[idx];
        S->sCb1[idx] = cb1[idx];
        S->sCw2[idx] = cW2[idx];
    }
    const float xi0 = x[row_i * 3 + 0];
    const float xi1 = x[row_i * 3 + 1];
    const float xi2 = x[row_i * 3 + 2];

    // per-lane ldmatrix address bases
    // A x4 (16x16): lanes 0-7 rows r0..r7 (k-lo), 8-15 rows r8..r15 (k-lo),
    //               16-23 rows r0..r7 (k-hi), 24-31 rows r8..r15 (k-hi)
    const uint32_t t1b = smem_u32(S->T1);
    const uint32_t w2b = smem_u32(S->W2);
    const uint32_t c1b = smem_u32(S->C1);
    const uint32_t aOff = (uint32_t)((rowbase + (lane & 7) + ((lane >> 3) & 1) * 8) * LDKB
                                     + ((lane >> 4) & 1) * 16);
    // B x4 (2 col-blocks of 8): lanes 0-7 n0..n7 (k-lo), 8-15 n0..n7 (k-hi),
    //                           16-23 n8..n15 (k-lo), 24-31 n8..n15 (k-hi)
    const uint32_t bOff = (uint32_t)((colbase + (lane & 7) + ((lane >> 4) & 1) * 8) * LDKB
                                     + ((lane >> 3) & 1) * 16);
    const uint32_t aAddr = t1b + aOff;
    const uint32_t bAddrW = w2b + bOff;
    const uint32_t bAddrC = c1b + bOff;

    float macc[16];
#pragma unroll
    for (int c = 0; c < 16; c++) macc[c] = 0.f;
    float cx = 0.f, cy = 0.f, cz = 0.f;
    __syncthreads();

    for (int jt = 0; jt < NTILES; jt++) {
        const int j0 = jt * TJ;

        // Phase A: distances + x_j
        if (t < TJ) {
            const int j = j0 + t;
            float x0 = x[(b * Nn + j) * 3 + 0];
            float x1 = x[(b * Nn + j) * 3 + 1];
            float x2 = x[(b * Nn + j) * 3 + 2];
            S->sx3[t * 3 + 0] = x0; S->sx3[t * 3 + 1] = x1; S->sx3[t * 3 + 2] = x2;
            float dx = xi0 - x0, dy = xi1 - x1, dz = xi2 - x2;
            S->SD[t] = dx * dx + dy * dy + dz * dz;
        }
        __syncthreads();

        // Phase B: T1 = silu_h2(f16(Ai + Bv_j + d*Wd)), 128x128
#pragma unroll
        for (int it = 0; it < 8; it++) {
            const int idx = t * 8 + it * NT * 8;
            const int m = idx >> 7, k = idx & 127;
            uint4 braw = *(const uint4*)&g_Bvh[(size_t)(b * Nn + j0 + m) * Hd + k];
            const __half2* bh = reinterpret_cast<const __half2*>(&braw);
            const float d = S->SD[m];
            uint4 pk;
            uint32_t* pko = reinterpret_cast<uint32_t*>(&pk);
#pragma unroll
            for (int q = 0; q < 4; q++) {
                float2 bv = __half22float2(bh[q]);
                const int kk = k + 2 * q;
                float p0 = S->sAi[kk]     + bv.x + d * S->sWd[kk];
                float p1 = S->sAi[kk + 1] + bv.y + d * S->sWd[kk + 1];
                pko[q] = h2u(silu_h2(__floats2half2_rn(p0, p1)));
            }
            *(uint4*)&S->T1[m * LDK + k] = pk;
        }
        __syncthreads();

        // GEMM1: acc = T1 @ eW2
        {
            float acc[16][4];
#pragma unroll
            for (int q = 0; q < 16; q++)
#pragma unroll
                for (int c = 0; c < 4; c++) acc[q][c] = 0.f;
            gemm_acc(aAddr, bAddrW, acc);
            __syncthreads();   // all reads of T1 complete before aliased write

            // Epilogue 1 (in place): T1 = silu_h2(acc + eb2), macc += colsums
            const int r0 = rowbase + g, r1 = r0 + 8, r2 = r0 + 16, r3 = r0 + 24;
#pragma unroll
            for (int nb = 0; nb < 8; nb++) {
                const int col = colbase + nb * 8 + 2 * tig;
                const float bb0 = S->sEb2[col], bb1 = S->sEb2[col + 1];
                __half2 s0 = silu_h2(__floats2half2_rn(acc[nb][0] + bb0,      acc[nb][1] + bb1));
                __half2 s1 = silu_h2(__floats2half2_rn(acc[nb][2] + bb0,      acc[nb][3] + bb1));
                __half2 s2 = silu_h2(__floats2half2_rn(acc[8 + nb][0] + bb0,  acc[8 + nb][1] + bb1));
                __half2 s3 = silu_h2(__floats2half2_rn(acc[8 + nb][2] + bb0,  acc[8 + nb][3] + bb1));
                *(uint32_t*)&S->T1[r0 * LDK + col] = h2u(s0);
                *(uint32_t*)&S->T1[r1 * LDK + col] = h2u(s1);
                *(uint32_t*)&S->T1[r2 * LDK + col] = h2u(s2);
                *(uint32_t*)&S->T1[r3 * LDK + col] = h2u(s3);
                float2 f0 = __half22float2(s0);
                float2 f1 = __half22float2(s1);
                float2 f2 = __half22float2(s2);
                float2 f3 = __half22float2(s3);
                macc[2 * nb]     += f0.x + f1.x + f2.x + f3.x;
                macc[2 * nb + 1] += f0.y + f1.y + f2.y + f3.y;
            }
        }
        __syncthreads();

        // GEMM2 + fused dot: P[cg][row] = dot(silu_h2(T1 @ cW1 + cb1), cW2)
        {
            float acc[16][4];
#pragma unroll
            for (int q = 0; q < 16; q++)
#pragma unroll
                for (int c = 0; c < 4; c++) acc[q][c] = 0.f;
            gemm_acc(aAddr, bAddrC, acc);
            float d0 = 0.f, d1 = 0.f, d2 = 0.f, d3 = 0.f;
#pragma unroll
            for (int nb = 0; nb < 8; nb++) {
                const int col = colbase + nb * 8 + 2 * tig;
                const float w0 = S->sCw2[col], w1 = S->sCw2[col + 1];
                const float bb0 = S->sCb1[col], bb1 = S->sCb1[col + 1];
                float2 f0 = __half22float2(silu_h2(__floats2half2_rn(acc[nb][0] + bb0,     acc[nb][1] + bb1)));
                float2 f1 = __half22float2(silu_h2(__floats2half2_rn(acc[nb][2] + bb0,     acc[nb][3] + bb1)));
                float2 f2 = __half22float2(silu_h2(__floats2half2_rn(acc[8 + nb][0] + bb0, acc[8 + nb][1] + bb1)));
                float2 f3 = __half22float2(silu_h2(__floats2half2_rn(acc[8 + nb][2] + bb0, acc[8 + nb][3] + bb1)));
                d0 += f0.x * w0 + f0.y * w1;
                d1 += f1.x * w0 + f1.y * w1;
                d2 += f2.x * w0 + f2.y * w1;
                d3 += f3.x * w0 + f3.y * w1;
            }
            d0 += __shfl_xor_sync(0xffffffffu, d0, 1); d0 += __shfl_xor_sync(0xffffffffu, d0, 2);
            d1 += __shfl_xor_sync(0xffffffffu, d1, 1); d1 += __shfl_xor_sync(0xffffffffu, d1, 2);
            d2 += __shfl_xor_sync(0xffffffffu, d2, 1); d2 += __shfl_xor_sync(0xffffffffu, d2, 2);
            d3 += __shfl_xor_sync(0xffffffffu, d3, 1); d3 += __shfl_xor_sync(0xffffffffu, d3, 2);
            if (tig == 0) {
                S->P[cg][rowbase + g]      = d0;
                S->P[cg][rowbase + g + 8]  = d1;
                S->P[cg][rowbase + g + 16] = d2;
                S->P[cg][rowbase + g + 24] = d3;
            }
        }
        __syncthreads();

        // coord accumulation over this tile
        if (t < TJ) {
            float wv = tanh_f(S->P[0][t] + S->P[1][t]);
            cx += (xi0 - S->sx3[t * 3 + 0]) * wv;
            cy += (xi1 - S->sx3[t * 3 + 1]) * wv;
            cz += (xi2 - S->sx3[t * 3 + 2]) * wv;
        }
        __syncthreads();
    }

    // magg: reduce lanes sharing columns, store per rowgroup
#pragma unroll
    for (int c = 0; c < 16; c++) {
        macc[c] += __shfl_down_sync(0xffffffffu, macc[c], 4);
        macc[c] += __shfl_down_sync(0xffffffffu, macc[c], 8);
        macc[c] += __shfl_down_sync(0xffffffffu, macc[c], 16);
    }
    if (lane < 4) {
#pragma unroll
        for (int nb = 0; nb < 8; nb++) {
            const int col = colbase + nb * 8 + 2 * lane;
            S->mred[wid & 3][col]     = macc[2 * nb];
            S->mred[wid & 3][col + 1] = macc[2 * nb + 1];
        }
    }

    // coord cross-warp reduce
    if (t < TJ) {
#pragma unroll
        for (int off = 16; off; off >>= 1) {
            cx += __shfl_down_sync(0xffffffffu, cx, off);
            cy += __shfl_down_sync(0xffffffffu, cy, off);
            cz += __shfl_down_sync(0xffffffffu, cz, off);
        }
        if (lane == 0) { S->csum[wid][0] = cx; S->csum[wid][1] = cy; S->csum[wid][2] = cz; }
    }
    __syncthreads();

    if (t < Hd) {
        float s = S->mred[0][t] + S->mred[1][t] + S->mred[2][t] + S->mred[3][t];
        g_magg[row_i * Hd + t] = s;
    }
    if (t == 0) {
        const float inv = 1.0f / (float)(Nn - 1);
        float s0 = S->csum[0][0] + S->csum[1][0] + S->csum[2][0] + S->csum[3][0];
        float s1 = S->csum[0][1] + S->csum[1][1] + S->csum[2][1] + S->csum[3][1];
        float s2 = S->csum[0][2] + S->csum[1][2] + S->csum[2][2] + S->csum[3][2];
        xout[row_i * 3 + 0] = xi0 + s0 * inv;
        xout[row_i * 3 + 1] = xi1 + s1 * inv;
        xout[row_i * 3 + 2] = xi2 + s2 * inv;
    }
}

// ---------------------------------------------------------------------------
// Node MLP: weights in SMEM, grid=128 (8 rows/CTA), float4 chunked loads
// ---------------------------------------------------------------------------
#define NODE_NR 8
struct __align__(16) NSmem {
    float W1[2 * Hd * Hd];
    float W2[Hd * Hd];
    float IN[NODE_NR][2 * Hd];
    float T[NODE_NR][Hd];
};

__global__ void __launch_bounds__(NT, 1)
node_kernel(const float* __restrict__ h,
            const float* __restrict__ nW1, const float* __restrict__ nb1,
            const float* __restrict__ nW2, const float* __restrict__ nb2,
            float* __restrict__ hout) {
    extern __shared__ __align__(16) unsigned char nsm_raw[];
    NSmem* S = reinterpret_cast<NSmem*>(nsm_raw);
    const int row0 = blockIdx.x * NODE_NR;
    const int t = threadIdx.x;

    {
        const uint4* s1 = (const uint4*)nW1;
        const uint4* s2 = (const uint4*)nW2;
        uint4* d1 = (uint4*)S->W1;
        uint4* d2 = (uint4*)S->W2;
        for (int idx = t; idx < 2 * Hd * Hd / 4; idx += NT) d1[idx] = s1[idx];
        for (int idx = t; idx < Hd * Hd / 4; idx += NT) d2[idx] = s2[idx];
    }
    for (int idx = t; idx < NODE_NR * 2 * Hd; idx += NT) {
        const int r = idx >> 8, c = idx & 255;
        S->IN[r][c] = (c < Hd) ? h[(row0 + r) * Hd + c]
                               : g_magg[(row0 + r) * Hd + (c - Hd)];
    }
    __syncthreads();

    const int k = t & 127, half = t >> 7;
    const int rb = half * 4;
    float acc[4];
    {
        const float b = nb1[k];
#pragma unroll
        for (int r = 0; r < 4; r++) acc[r] = b;
    }
#pragma unroll 4
    for (int c0 = 0; c0 < 2 * Hd; c0 += 4) {
        float4 in0 = *(const float4*)&S->IN[rb + 0][c0];
        float4 in1 = *(const float4*)&S->IN[rb + 1][c0];
        float4 in2 = *(const float4*)&S->IN[rb + 2][c0];
        float4 in3 = *(const float4*)&S->IN[rb + 3][c0];
        float w0 = S->W1[(c0 + 0) * Hd + k];
        float w1 = S->W1[(c0 + 1) * Hd + k];
        float w2 = S->W1[(c0 + 2) * Hd + k];
        float w3 = S->W1[(c0 + 3) * Hd + k];
        acc[0] = fmaf(in0.x, w0, fmaf(in0.y, w1, fmaf(in0.z, w2, fmaf(in0.w, w3, acc[0]))));
        acc[1] = fmaf(in1.x, w0, fmaf(in1.y, w1, fmaf(in1.z, w2, fmaf(in1.w, w3, acc[1]))));
        acc[2] = fmaf(in2.x, w0, fmaf(in2.y, w1, fmaf(in2.z, w2, fmaf(in2.w, w3, acc[2]))));
        acc[3] = fmaf(in3.x, w0, fmaf(in3.y, w1, fmaf(in3.z, w2, fmaf(in3.w, w3, acc[3]))));
    }
#pragma unroll
    for (int r = 0; r < 4; r++) S->T[rb + r][k] = silu_f(acc[r]);
    __syncthreads();
    float o[4];
    {
        const float b = nb2[k];
#pragma unroll
        for (int r = 0; r < 4; r++) o[r] = b;
    }
#pragma unroll 4
    for (int c0 = 0; c0 < Hd; c0 += 4) {
        float4 t0 = *(const float4*)&S->T[rb + 0][c0];
        float4 t1 = *(const float4*)&S->T[rb + 1][c0];
        float4 t2 = *(const float4*)&S->T[rb + 2][c0];
        float4 t3 = *(const float4*)&S->T[rb + 3][c0];
        float w0 = S->W2[(c0 + 0) * Hd + k];
        float w1 = S->W2[(c0 + 1) * Hd + k];
        float w2 = S->W2[(c0 + 2) * Hd + k];
        float w3 = S->W2[(c0 + 3) * Hd + k];
        o[0] = fmaf(t0.x, w0, fmaf(t0.y, w1, fmaf(t0.z, w2, fmaf(t0.w, w3, o[0]))));
        o[1] = fmaf(t1.x, w0, fmaf(t1.y, w1, fmaf(t1.z, w2, fmaf(t1.w, w3, o[1]))));
        o[2] = fmaf(t2.x, w0, fmaf(t2.y, w1, fmaf(t2.z, w2, fmaf(t2.w, w3, o[2]))));
        o[3] = fmaf(t3.x, w0, fmaf(t3.y, w1, fmaf(t3.z, w2, fmaf(t3.w, w3, o[3]))));
    }
#pragma unroll
    for (int r = 0; r < 4; r++)
        hout[(row0 + rb + r) * Hd + k] = S->IN[rb + r][k] + o[r];
}

// ---------------------------------------------------------------------------
extern "C" void kernel_launch(void* const* d_in, const int* in_sizes, int n_in,
                              void* d_out, int out_size) {
    const float* h   = (const float*)d_in[0];
    const float* x   = (const float*)d_in[1];
    const float* eW1 = (const float*)d_in[2];
    const float* eb1 = (const float*)d_in[3];
    const float* eW2 = (const float*)d_in[4];
    const float* eb2 = (const float*)d_in[5];
    const float* nW1 = (const float*)d_in[6];
    const float* nb1 = (const float*)d_in[7];
    const float* nW2 = (const float*)d_in[8];
    const float* nb2 = (const float*)d_in[9];
    const float* cW1 = (const float*)d_in[10];
    const float* cb1 = (const float*)d_in[11];
    const float* cW2 = (const float*)d_in[12];

    float* out  = (float*)d_out;
    float* hout = out;
    float* xout = out + Bb * Nn * Hd;

    convert_w_kernel<<<64, 256>>>(eW2, cW1);
    precompute_kernel<<<Bb * Nn / 16, NT>>>(h, eW1, eb1);

    const int smem = (int)sizeof(ESmem);
    cudaFuncSetAttribute(edge_kernel, cudaFuncAttributeMaxDynamicSharedMemorySize, smem);
    dim3 grid(Nn, Bb);
    edge_kernel<<<grid, NT, smem>>>(x, eW1, eb2, cb1, cW2, xout);

    const int nsmem = (int)sizeof(NSmem);
    cudaFuncSetAttribute(node_kernel, cudaFuncAttributeMaxDynamicSharedMemorySize, nsmem);
    node_kernel<<<Bb * Nn / NODE_NR, NT, nsmem>>>(h, nW1, nb1, nW2, nb2, hout);
}